// round 1
// baseline (speedup 1.0000x reference)
#include <cuda_runtime.h>
#include <cuda_bf16.h>

// Problem constants (fixed by reference setup_inputs)
#define BB 8
#define NN 1024
#define BN 8192          // B*N
#define INF 128
#define OUTF 256
#define NH 4
#define DD 64

// Scratch (device globals: no allocation allowed in kernel_launch)
__device__ float g_h[BN * OUTF];          // h = x @ W   [8192][256]
__device__ float g_si[NH * BN];
__device__ float g_sj[NH * BN];
__device__ float g_Ei[NH * BN];
__device__ float g_Fi[NH * BN];
__device__ float g_Ej[NH * BN];
__device__ float g_Fj[NH * BN];

// ---------------------------------------------------------------------------
// Kernel A: SGEMM  g_h[8192,256] = x[8192,128] @ W[128,256]
// 128x128 tile, BK=16, 256 threads, 8x8 microtile
// ---------------------------------------------------------------------------
__global__ __launch_bounds__(256) void k_gemm(const float* __restrict__ A,
                                              const float* __restrict__ W) {
    __shared__ float As[16][132];   // [k][m], padded
    __shared__ float Bs[16][128];   // [k][n]

    const int tid = threadIdx.x;
    const int m0 = blockIdx.x * 128;
    const int n0 = blockIdx.y * 128;
    const int tm = (tid >> 4) * 8;
    const int tn = (tid & 15) * 8;

    float acc[8][8];
#pragma unroll
    for (int u = 0; u < 8; u++)
#pragma unroll
        for (int v = 0; v < 8; v++) acc[u][v] = 0.f;

    for (int k0 = 0; k0 < 128; k0 += 16) {
        // load A tile 128x16 (512 float4, 2/thread), store transposed
#pragma unroll
        for (int q = 0; q < 2; q++) {
            int f = tid + q * 256;            // 0..511
            int r = f >> 2;                   // row within tile 0..127
            int c = (f & 3) * 4;              // k offset 0,4,8,12
            float4 v = *(const float4*)(A + (size_t)(m0 + r) * 128 + k0 + c);
            As[c + 0][r] = v.x;
            As[c + 1][r] = v.y;
            As[c + 2][r] = v.z;
            As[c + 3][r] = v.w;
        }
        // load B tile 16x128
#pragma unroll
        for (int q = 0; q < 2; q++) {
            int f = tid + q * 256;
            int r = f >> 5;                   // 0..15
            int c = (f & 31) * 4;             // 0..124
            *(float4*)&Bs[r][c] = *(const float4*)(W + (size_t)(k0 + r) * 256 + n0 + c);
        }
        __syncthreads();

#pragma unroll
        for (int k = 0; k < 16; k++) {
            float af[8], bf[8];
#pragma unroll
            for (int u = 0; u < 8; u++) af[u] = As[k][tm + u];
#pragma unroll
            for (int v = 0; v < 8; v++) bf[v] = Bs[k][tn + v];
#pragma unroll
            for (int u = 0; u < 8; u++)
#pragma unroll
                for (int v = 0; v < 8; v++) acc[u][v] += af[u] * bf[v];
        }
        __syncthreads();
    }

#pragma unroll
    for (int u = 0; u < 8; u++) {
        float* cp = g_h + (size_t)(m0 + tm + u) * 256 + n0 + tn;
        *(float4*)(cp + 0) = make_float4(acc[u][0], acc[u][1], acc[u][2], acc[u][3]);
        *(float4*)(cp + 4) = make_float4(acc[u][4], acc[u][5], acc[u][6], acc[u][7]);
    }
}

// ---------------------------------------------------------------------------
// Kernel B: per-node scores s_i = <h[n,h,:], a[:64]>, s_j = <h[n,h,:], a[64:]>
// plus the 4 exp factors per (n,h). One warp per node.
// ---------------------------------------------------------------------------
__global__ __launch_bounds__(256) void k_scores(const float* __restrict__ a) {
    const int warp = threadIdx.x >> 5;
    const int lane = threadIdx.x & 31;
    const int n = blockIdx.x * 8 + warp;

    const float* hr = g_h + (size_t)n * 256;

    float sip[4] = {0.f, 0.f, 0.f, 0.f};
    float sjp[4] = {0.f, 0.f, 0.f, 0.f};
#pragma unroll
    for (int q = 0; q < 8; q++) {
        int c = q * 32 + lane;
        float v = hr[c];
        int head = q >> 1;                    // compile-time per unrolled iter
        int d = (q & 1) * 32 + lane;
        sip[head] += v * a[d];
        sjp[head] += v * a[64 + d];
    }
#pragma unroll
    for (int hh = 0; hh < 4; hh++) {
#pragma unroll
        for (int o = 16; o; o >>= 1) {
            sip[hh] += __shfl_xor_sync(0xFFFFFFFFu, sip[hh], o);
            sjp[hh] += __shfl_xor_sync(0xFFFFFFFFu, sjp[hh], o);
        }
    }
    if (lane == 0) {
#pragma unroll
        for (int hh = 0; hh < 4; hh++) {
            int o = hh * BN + n;
            float si = sip[hh], sj = sjp[hh];
            g_si[o] = si;
            g_sj[o] = sj;
            g_Ei[o] = __expf(si);
            g_Fi[o] = __expf(0.2f * si);
            g_Ej[o] = __expf(sj);
            g_Fj[o] = __expf(0.2f * sj);
        }
    }
}

// ---------------------------------------------------------------------------
// Kernel C: fused masked-softmax aggregation.
// Block = (h, i-tile of 64, b). grid (4, 16, 8) — h fastest for adjacency L2 reuse.
// w_ij = adj ? ((s_i+s_j>=0) ? Ei*Ej : Fi*Fj) : 0
// out[i,d] = sum_j w_ij * h[j,d] / sum_j w_ij
// ---------------------------------------------------------------------------
__global__ __launch_bounds__(256) void k_aggr(const int* __restrict__ adj,
                                              float* __restrict__ out) {
    __shared__ float Hs[64][64];       // [j][d]
    __shared__ float Ws[64][64];       // [j][i]
    __shared__ float sjs[NN];
    __shared__ float Ejs[NN];
    __shared__ float Fjs[NN];
    __shared__ float den[64];

    const int tid = threadIdx.x;
    const int h  = blockIdx.x;
    const int it = blockIdx.y;
    const int b  = blockIdx.z;
    const int i0 = it * 64;
    const int hoff = h * BN + b * NN;

    // preload all j-side scalars for this (b,h)
    for (int idx = tid; idx < NN; idx += 256) {
        sjs[idx] = g_sj[hoff + idx];
        Ejs[idx] = g_Ej[hoff + idx];
        Fjs[idx] = g_Fj[hoff + idx];
    }

    // w-gen mapping: thread -> (iw, 16-wide j segment)
    const int iw   = tid >> 2;             // 0..63
    const int jseg = (tid & 3) * 16;
    const float si_i = g_si[hoff + i0 + iw];
    const float Ei_i = g_Ei[hoff + i0 + iw];
    const float Fi_i = g_Fi[hoff + i0 + iw];

    // FMA mapping: 16x16 threads, 4i x 4d microtile
    const int ti4 = (tid >> 4) * 4;        // i base
    const int td4 = (tid & 15) * 4;        // d base
    const bool is_d0 = ((tid & 15) == 0);

    float acc[4][4];
#pragma unroll
    for (int u = 0; u < 4; u++)
#pragma unroll
        for (int v = 0; v < 4; v++) acc[u][v] = 0.f;
    float dsum[4] = {0.f, 0.f, 0.f, 0.f};

    const float* hbase = g_h + (size_t)(b * NN) * 256 + h * 64;
    const int*   arow  = adj + (size_t)(b * NN + i0 + iw) * NN + jseg;

    __syncthreads();   // sjs/Ejs/Fjs ready

    for (int j0 = 0; j0 < NN; j0 += 64) {
        // load H chunk [64 j][64 d]
#pragma unroll
        for (int q = 0; q < 4; q++) {
            int f = tid + q * 256;             // float4 index 0..1023
            int jj = f >> 4;
            int c = (f & 15) * 4;
            *(float4*)&Hs[jj][c] = *(const float4*)(hbase + (size_t)(j0 + jj) * 256 + c);
        }
        // generate W chunk (16 entries per thread)
        {
            const int4* ap = (const int4*)(arow + j0);
#pragma unroll
            for (int s = 0; s < 4; s++) {
                int4 av = ap[s];
                int jb = jseg + s * 4;
                {
                    float t = si_i + sjs[j0 + jb + 0];
                    float w = (t >= 0.f) ? Ei_i * Ejs[j0 + jb + 0] : Fi_i * Fjs[j0 + jb + 0];
                    Ws[jb + 0][iw] = (av.x != 0) ? w : 0.f;
                }
                {
                    float t = si_i + sjs[j0 + jb + 1];
                    float w = (t >= 0.f) ? Ei_i * Ejs[j0 + jb + 1] : Fi_i * Fjs[j0 + jb + 1];
                    Ws[jb + 1][iw] = (av.y != 0) ? w : 0.f;
                }
                {
                    float t = si_i + sjs[j0 + jb + 2];
                    float w = (t >= 0.f) ? Ei_i * Ejs[j0 + jb + 2] : Fi_i * Fjs[j0 + jb + 2];
                    Ws[jb + 2][iw] = (av.z != 0) ? w : 0.f;
                }
                {
                    float t = si_i + sjs[j0 + jb + 3];
                    float w = (t >= 0.f) ? Ei_i * Ejs[j0 + jb + 3] : Fi_i * Fjs[j0 + jb + 3];
                    Ws[jb + 3][iw] = (av.w != 0) ? w : 0.f;
                }
            }
        }
        __syncthreads();

        // accumulate
#pragma unroll 8
        for (int j = 0; j < 64; j++) {
            float4 wv = *(const float4*)&Ws[j][ti4];
            float4 hv = *(const float4*)&Hs[j][td4];
            acc[0][0] += wv.x * hv.x; acc[0][1] += wv.x * hv.y;
            acc[0][2] += wv.x * hv.z; acc[0][3] += wv.x * hv.w;
            acc[1][0] += wv.y * hv.x; acc[1][1] += wv.y * hv.y;
            acc[1][2] += wv.y * hv.z; acc[1][3] += wv.y * hv.w;
            acc[2][0] += wv.z * hv.x; acc[2][1] += wv.z * hv.y;
            acc[2][2] += wv.z * hv.z; acc[2][3] += wv.z * hv.w;
            acc[3][0] += wv.w * hv.x; acc[3][1] += wv.w * hv.y;
            acc[3][2] += wv.w * hv.z; acc[3][3] += wv.w * hv.w;
            if (is_d0) {
                dsum[0] += wv.x; dsum[1] += wv.y;
                dsum[2] += wv.z; dsum[3] += wv.w;
            }
        }
        __syncthreads();
    }

    if (is_d0) {
        den[ti4 + 0] = dsum[0];
        den[ti4 + 1] = dsum[1];
        den[ti4 + 2] = dsum[2];
        den[ti4 + 3] = dsum[3];
    }
    __syncthreads();

#pragma unroll
    for (int u = 0; u < 4; u++) {
        float r = 1.0f / den[ti4 + u];
        float4 o;
        o.x = acc[u][0] * r;
        o.y = acc[u][1] * r;
        o.z = acc[u][2] * r;
        o.w = acc[u][3] * r;
        *(float4*)(out + (size_t)(b * NN + i0 + ti4 + u) * 256 + h * 64 + td4) = o;
    }
}

// ---------------------------------------------------------------------------
extern "C" void kernel_launch(void* const* d_in, const int* in_sizes, int n_in,
                              void* d_out, int out_size) {
    const float* x   = (const float*)d_in[0];   // [8,1024,128]
    const int*   adj = (const int*)d_in[1];     // [8,1024,1024]
    const float* W   = (const float*)d_in[2];   // [128,256]
    const float* a   = (const float*)d_in[3];   // [128]
    float* out = (float*)d_out;                 // [8,1024,256]

    k_gemm<<<dim3(BN / 128, OUTF / 128), 256>>>(x, W);
    k_scores<<<BN / 8, 256>>>(a);
    k_aggr<<<dim3(NH, NN / 64, BB), 256>>>(adj, out);
}

// round 2
// speedup vs baseline: 2.3486x; 2.3486x over previous
#include <cuda_runtime.h>
#include <cuda_fp16.h>
#include <cuda_bf16.h>

// Problem constants (fixed by reference setup_inputs)
#define BB 8
#define NN 1024
#define BN 8192          // B*N
#define INF 128
#define OUTF 256
#define NH 4
#define DD 64

// Scratch (device globals: no allocation allowed in kernel_launch)
__device__ float g_h[BN * OUTF];            // h = x @ W  fp32 [8192][256]
__device__ __half g_h16[BN * OUTF];         // fp16 copy for MMA B operand
__device__ float g_si[NH * BN];
__device__ float g_sj[NH * BN];
__device__ float g_Ei[NH * BN];
__device__ float g_Fi[NH * BN];
__device__ float g_Ej[NH * BN];
__device__ float g_Fj[NH * BN];

// ---------------------------------------------------------------------------
// Kernel A: SGEMM  g_h[8192,256] = x[8192,128] @ W[128,256]  (+ fp16 copy)
// 128x128 tile, BK=16, 256 threads, 8x8 microtile, 2 blocks/SM
// ---------------------------------------------------------------------------
__global__ __launch_bounds__(256, 2) void k_gemm(const float* __restrict__ A,
                                                 const float* __restrict__ W) {
    __shared__ float As[16][132];   // [k][m], padded
    __shared__ float Bs[16][128];   // [k][n]

    const int tid = threadIdx.x;
    const int m0 = blockIdx.x * 128;
    const int n0 = blockIdx.y * 128;
    const int tm = (tid >> 4) * 8;
    const int tn = (tid & 15) * 8;

    float acc[8][8];
#pragma unroll
    for (int u = 0; u < 8; u++)
#pragma unroll
        for (int v = 0; v < 8; v++) acc[u][v] = 0.f;

    for (int k0 = 0; k0 < 128; k0 += 16) {
#pragma unroll
        for (int q = 0; q < 2; q++) {
            int f = tid + q * 256;
            int r = f >> 2;
            int c = (f & 3) * 4;
            float4 v = *(const float4*)(A + (size_t)(m0 + r) * 128 + k0 + c);
            As[c + 0][r] = v.x;
            As[c + 1][r] = v.y;
            As[c + 2][r] = v.z;
            As[c + 3][r] = v.w;
        }
#pragma unroll
        for (int q = 0; q < 2; q++) {
            int f = tid + q * 256;
            int r = f >> 5;
            int c = (f & 31) * 4;
            *(float4*)&Bs[r][c] = *(const float4*)(W + (size_t)(k0 + r) * 256 + n0 + c);
        }
        __syncthreads();

#pragma unroll
        for (int k = 0; k < 16; k++) {
            float af[8], bf[8];
#pragma unroll
            for (int u = 0; u < 8; u++) af[u] = As[k][tm + u];
#pragma unroll
            for (int v = 0; v < 8; v++) bf[v] = Bs[k][tn + v];
#pragma unroll
            for (int u = 0; u < 8; u++)
#pragma unroll
                for (int v = 0; v < 8; v++) acc[u][v] += af[u] * bf[v];
        }
        __syncthreads();
    }

#pragma unroll
    for (int u = 0; u < 8; u++) {
        size_t row = (size_t)(m0 + tm + u);
        float* cp = g_h + row * 256 + n0 + tn;
        *(float4*)(cp + 0) = make_float4(acc[u][0], acc[u][1], acc[u][2], acc[u][3]);
        *(float4*)(cp + 4) = make_float4(acc[u][4], acc[u][5], acc[u][6], acc[u][7]);
        // fp16 copy (8 halves = 16B)
        __half2 hp[4];
#pragma unroll
        for (int v = 0; v < 4; v++)
            hp[v] = __floats2half2_rn(acc[u][2 * v], acc[u][2 * v + 1]);
        *(uint4*)(g_h16 + row * 256 + n0 + tn) = *(uint4*)hp;
    }
}

// ---------------------------------------------------------------------------
// Kernel B: per-node scores + exp factors. One warp per node.
// ---------------------------------------------------------------------------
__global__ __launch_bounds__(256) void k_scores(const float* __restrict__ a) {
    const int warp = threadIdx.x >> 5;
    const int lane = threadIdx.x & 31;
    const int n = blockIdx.x * 8 + warp;

    const float* hr = g_h + (size_t)n * 256;

    float sip[4] = {0.f, 0.f, 0.f, 0.f};
    float sjp[4] = {0.f, 0.f, 0.f, 0.f};
#pragma unroll
    for (int q = 0; q < 8; q++) {
        int c = q * 32 + lane;
        float v = hr[c];
        int head = q >> 1;
        int d = (q & 1) * 32 + lane;
        sip[head] += v * a[d];
        sjp[head] += v * a[64 + d];
    }
#pragma unroll
    for (int hh = 0; hh < 4; hh++) {
#pragma unroll
        for (int o = 16; o; o >>= 1) {
            sip[hh] += __shfl_xor_sync(0xFFFFFFFFu, sip[hh], o);
            sjp[hh] += __shfl_xor_sync(0xFFFFFFFFu, sjp[hh], o);
        }
    }
    if (lane == 0) {
#pragma unroll
        for (int hh = 0; hh < 4; hh++) {
            int o = hh * BN + n;
            float si = sip[hh], sj = sjp[hh];
            g_si[o] = si;
            g_sj[o] = sj;
            g_Ei[o] = __expf(si);
            g_Fi[o] = __expf(0.2f * si);
            g_Ej[o] = __expf(sj);
            g_Fj[o] = __expf(0.2f * sj);
        }
    }
}

// ---------------------------------------------------------------------------
// Kernel C: tensor-core masked-softmax aggregation.
// Block = (b, 64-row i-tile), 512 threads = 16 warps = 4 i-groups x 4 heads.
// Adjacency read ONCE (all heads per block). P (A-operand) generated directly
// in mma fragment registers. B = h16 [64 j][256 d] + ones col 256 -> 9th
// n-tile yields the softmax denominator consistent with fp16 numerator.
// ---------------------------------------------------------------------------
#define BS_STRIDE 264            // halves per Bs row (256 d + ones col + pad)
#define SM_BS_BYTES (64 * BS_STRIDE * 2)             // 33792
#define SM_SJ_OFF   SM_BS_BYTES                      // float [4][1024]
#define SM_EF_OFF   (SM_BS_BYTES + 16384)            // half2 [4][1024]
#define SM_TOTAL    (SM_BS_BYTES + 16384 + 16384)    // 66560 B

__global__ void k_aggr(const int* __restrict__ adj,
                       float* __restrict__ out) {
    extern __shared__ char smem[];
    __half*  Bs  = (__half*)smem;                    // [64][BS_STRIDE]
    float*   sjs = (float*)(smem + SM_SJ_OFF);       // [h][j]
    __half2* EFs = (__half2*)(smem + SM_EF_OFF);     // [h][j] = (Ej, Fj)

    const int tid  = threadIdx.x;
    const int lane = tid & 31;
    const int warp = tid >> 5;
    const int wi   = warp & 3;            // i-group (16 rows)
    const int hh   = warp >> 2;           // head
    const int it   = blockIdx.x;
    const int b    = blockIdx.y;
    const int i0   = it * 64;

    // ---- preload per-(b,h) j-side scalars into smem ----
    for (int idx = tid; idx < NH * NN; idx += 512) {
        int h = idx >> 10, j = idx & 1023;
        int o = h * BN + b * NN + j;
        sjs[idx] = g_sj[o];
        EFs[idx] = __floats2half2_rn(g_Ej[o], g_Fj[o]);
    }
    // ones column (cols 256..263; copy loop never touches them)
    if (tid < 64) {
        Bs[tid * BS_STRIDE + 256] = __float2half(1.0f);
#pragma unroll
        for (int c = 257; c < 264; c++) Bs[tid * BS_STRIDE + c] = __float2half(0.0f);
    }

    // ---- per-thread i-side scalars (2 rows of this warp's m16) ----
    const int hoff = hh * BN + b * NN;
    const int ilo = wi * 16 + (lane >> 2);      // local row 0..15
    const int ihi = ilo + 8;
    const float si_lo = g_si[hoff + i0 + ilo];
    const float Ei_lo = g_Ei[hoff + i0 + ilo];
    const float Fi_lo = g_Fi[hoff + i0 + ilo];
    const float si_hi = g_si[hoff + i0 + ihi];
    const float Ei_hi = g_Ei[hoff + i0 + ihi];
    const float Fi_hi = g_Fi[hoff + i0 + ihi];

    const int* arow_lo = adj + ((size_t)b * NN + i0 + ilo) * NN;
    const int* arow_hi = adj + ((size_t)b * NN + i0 + ihi) * NN;
    const float*   sjp = sjs + hh * NN;
    const __half2* efp = EFs + hh * NN;

    float acc[9][4];
#pragma unroll
    for (int t = 0; t < 9; t++)
#pragma unroll
        for (int v = 0; v < 4; v++) acc[t][v] = 0.f;

    const __half* h16b = g_h16 + (size_t)b * NN * 256;
    const int jcol = (lane & 3) * 2;            // k-col pair base within k16

    __syncthreads();   // sjs/EFs/ones ready

    for (int j0 = 0; j0 < NN; j0 += 64) {
        // ---- load B tile: h16 rows [j0..j0+64) x 256 cols ----
        {
            int jj  = tid >> 3;                  // 0..63
            int seg = (tid & 7) * 32;            // halves
            const uint4* src = (const uint4*)(h16b + (size_t)(j0 + jj) * 256 + seg);
            uint4* dst = (uint4*)(Bs + jj * BS_STRIDE + seg);
#pragma unroll
            for (int q = 0; q < 4; q++) dst[q] = src[q];
        }
        __syncthreads();

#pragma unroll
        for (int ks = 0; ks < 4; ks++) {
            const int jb = j0 + ks * 16 + jcol;  // even
            // adjacency pairs for this thread's fragment coords
            int2 alo0 = *(const int2*)(arow_lo + jb);
            int2 alo8 = *(const int2*)(arow_lo + jb + 8);
            int2 ahi0 = *(const int2*)(arow_hi + jb);
            int2 ahi8 = *(const int2*)(arow_hi + jb + 8);

            // generate A fragment (w values) in registers
            unsigned a0, a1, a2, a3;
            {
                float sj0 = sjp[jb], sj1 = sjp[jb + 1];
                __half2 e0 = efp[jb], e1 = efp[jb + 1];
                float Ej0 = __low2float(e0), Fj0 = __high2float(e0);
                float Ej1 = __low2float(e1), Fj1 = __high2float(e1);
                float w0 = alo0.x ? ((si_lo + sj0 >= 0.f) ? Ei_lo * Ej0 : Fi_lo * Fj0) : 0.f;
                float w1 = alo0.y ? ((si_lo + sj1 >= 0.f) ? Ei_lo * Ej1 : Fi_lo * Fj1) : 0.f;
                __half2 p = __floats2half2_rn(w0, w1);
                a0 = *(unsigned*)&p;
                float v0 = ahi0.x ? ((si_hi + sj0 >= 0.f) ? Ei_hi * Ej0 : Fi_hi * Fj0) : 0.f;
                float v1 = ahi0.y ? ((si_hi + sj1 >= 0.f) ? Ei_hi * Ej1 : Fi_hi * Fj1) : 0.f;
                __half2 q = __floats2half2_rn(v0, v1);
                a1 = *(unsigned*)&q;
            }
            {
                float sj0 = sjp[jb + 8], sj1 = sjp[jb + 9];
                __half2 e0 = efp[jb + 8], e1 = efp[jb + 9];
                float Ej0 = __low2float(e0), Fj0 = __high2float(e0);
                float Ej1 = __low2float(e1), Fj1 = __high2float(e1);
                float w0 = alo8.x ? ((si_lo + sj0 >= 0.f) ? Ei_lo * Ej0 : Fi_lo * Fj0) : 0.f;
                float w1 = alo8.y ? ((si_lo + sj1 >= 0.f) ? Ei_lo * Ej1 : Fi_lo * Fj1) : 0.f;
                __half2 p = __floats2half2_rn(w0, w1);
                a2 = *(unsigned*)&p;
                float v0 = ahi8.x ? ((si_hi + sj0 >= 0.f) ? Ei_hi * Ej0 : Fi_hi * Fj0) : 0.f;
                float v1 = ahi8.y ? ((si_hi + sj1 >= 0.f) ? Ei_hi * Ej1 : Fi_hi * Fj1) : 0.f;
                __half2 q = __floats2half2_rn(v0, v1);
                a3 = *(unsigned*)&q;
            }

            // B fragments via ldmatrix.trans from Bs rows k = j0-chunk-local
            const int krow = ks * 16 + (lane & 15);
            unsigned bt[9][2];
#pragma unroll
            for (int p = 0; p < 4; p++) {
                int n0 = hh * 64 + p * 16 + ((lane >> 4) << 3);
                unsigned addr = (unsigned)__cvta_generic_to_shared(
                    Bs + krow * BS_STRIDE + n0);
                asm volatile(
                    "ldmatrix.sync.aligned.m8n8.x4.trans.shared.b16 {%0,%1,%2,%3}, [%4];"
                    : "=r"(bt[2 * p][0]), "=r"(bt[2 * p][1]),
                      "=r"(bt[2 * p + 1][0]), "=r"(bt[2 * p + 1][1])
                    : "r"(addr));
            }
            {
                unsigned addr = (unsigned)__cvta_generic_to_shared(
                    Bs + krow * BS_STRIDE + 256);
                asm volatile(
                    "ldmatrix.sync.aligned.m8n8.x2.trans.shared.b16 {%0,%1}, [%2];"
                    : "=r"(bt[8][0]), "=r"(bt[8][1]) : "r"(addr));
            }

#pragma unroll
            for (int t = 0; t < 9; t++) {
                asm volatile(
                    "mma.sync.aligned.m16n8k16.row.col.f32.f16.f16.f32 "
                    "{%0,%1,%2,%3}, {%4,%5,%6,%7}, {%8,%9}, {%0,%1,%2,%3};"
                    : "+f"(acc[t][0]), "+f"(acc[t][1]), "+f"(acc[t][2]), "+f"(acc[t][3])
                    : "r"(a0), "r"(a1), "r"(a2), "r"(a3),
                      "r"(bt[t][0]), "r"(bt[t][1]));
            }
        }
        __syncthreads();   // before Bs is overwritten next chunk
    }

    // ---- epilogue: denominators from ones-tile frag, divide, store ----
    float den_lo = __shfl_sync(0xFFFFFFFFu, acc[8][0], lane & 28);
    float den_hi = __shfl_sync(0xFFFFFFFFu, acc[8][2], lane & 28);
    float inv_lo = 1.0f / den_lo;
    float inv_hi = 1.0f / den_hi;

    const size_t row_lo = (size_t)b * NN + i0 + ilo;
    const size_t row_hi = (size_t)b * NN + i0 + ihi;
#pragma unroll
    for (int t = 0; t < 8; t++) {
        int col = hh * 64 + t * 8 + (lane & 3) * 2;
        float2 vlo = make_float2(acc[t][0] * inv_lo, acc[t][1] * inv_lo);
        float2 vhi = make_float2(acc[t][2] * inv_hi, acc[t][3] * inv_hi);
        *(float2*)(out + row_lo * 256 + col) = vlo;
        *(float2*)(out + row_hi * 256 + col) = vhi;
    }
}

// ---------------------------------------------------------------------------
extern "C" void kernel_launch(void* const* d_in, const int* in_sizes, int n_in,
                              void* d_out, int out_size) {
    const float* x   = (const float*)d_in[0];   // [8,1024,128]
    const int*   adj = (const int*)d_in[1];     // [8,1024,1024]
    const float* W   = (const float*)d_in[2];   // [128,256]
    const float* a   = (const float*)d_in[3];   // [128]
    float* out = (float*)d_out;                 // [8,1024,256]

    cudaFuncSetAttribute(k_aggr, cudaFuncAttributeMaxDynamicSharedMemorySize,
                         SM_TOTAL);

    k_gemm<<<dim3(BN / 128, OUTF / 128), 256>>>(x, W);
    k_scores<<<BN / 8, 256>>>(a);
    k_aggr<<<dim3(NN / 64, BB), 512, SM_TOTAL>>>(adj, out);
}

// round 3
// speedup vs baseline: 2.9339x; 1.2492x over previous
#include <cuda_runtime.h>
#include <cuda_fp16.h>
#include <cuda_bf16.h>

// Problem constants (fixed by reference setup_inputs)
#define BB 8
#define NN 1024
#define BN 8192          // B*N
#define INF 128
#define OUTF 256
#define NH 4
#define DD 64

// Scratch (device globals)
__device__ __half g_h16[BN * OUTF];         // h in fp16 (MMA B operand)
__device__ float g_si[NH * BN];
__device__ float g_sj[NH * BN];
__device__ float g_Ei[NH * BN];
__device__ float g_Fi[NH * BN];
__device__ float g_Ej[NH * BN];
__device__ float g_Fj[NH * BN];

// cp.async helpers
__device__ __forceinline__ void cp16(unsigned dst, const void* src) {
    asm volatile("cp.async.cg.shared.global [%0], [%1], 16;" :: "r"(dst), "l"(src));
}
__device__ __forceinline__ void cp_commit() {
    asm volatile("cp.async.commit_group;");
}
__device__ __forceinline__ void cp_wait0() {
    asm volatile("cp.async.wait_group 0;");
}

// ---------------------------------------------------------------------------
// Kernel A: SGEMM h = x @ W (fp32 math, fp16 store) FUSED with per-node
// attention scores. 64x64 tiles, BK=32, 256 threads, 4x4 microtile.
// Each block covers one head's 64 cols -> computes s_i/s_j + exp factors.
// ---------------------------------------------------------------------------
__global__ __launch_bounds__(256) void k_gemm(const float* __restrict__ x,
                                              const float* __restrict__ W,
                                              const float* __restrict__ a) {
    __shared__ float As[32 * 65];     // [k][m] stride 65 (conflict-free)
    __shared__ float Bs[32 * 68];     // [k][n] stride 68 (f4-aligned)

    const int tid = threadIdx.x;
    const int m0 = blockIdx.x * 64;
    const int n0 = blockIdx.y * 64;
    const int row = (tid >> 4) * 4;
    const int col = (tid & 15) * 4;

    float acc[4][4];
#pragma unroll
    for (int u = 0; u < 4; u++)
#pragma unroll
        for (int v = 0; v < 4; v++) acc[u][v] = 0.f;

    for (int k0 = 0; k0 < 128; k0 += 32) {
#pragma unroll
        for (int q = 0; q < 2; q++) {
            int f = tid + q * 256;            // 0..511
            int r = f >> 3;                   // 0..63 (m)
            int c4 = (f & 7) * 4;             // k offset
            float4 v = *(const float4*)(x + (size_t)(m0 + r) * 128 + k0 + c4);
            As[(c4 + 0) * 65 + r] = v.x;
            As[(c4 + 1) * 65 + r] = v.y;
            As[(c4 + 2) * 65 + r] = v.z;
            As[(c4 + 3) * 65 + r] = v.w;
        }
#pragma unroll
        for (int q = 0; q < 2; q++) {
            int f = tid + q * 256;
            int r = f >> 4;                   // 0..31 (k)
            int c = (f & 15) * 4;             // n
            *(float4*)&Bs[r * 68 + c] = *(const float4*)(W + (size_t)(k0 + r) * 256 + n0 + c);
        }
        __syncthreads();

#pragma unroll
        for (int k = 0; k < 32; k++) {
            float af[4];
#pragma unroll
            for (int u = 0; u < 4; u++) af[u] = As[k * 65 + row + u];
            float4 bf = *(const float4*)&Bs[k * 68 + col];
#pragma unroll
            for (int u = 0; u < 4; u++) {
                acc[u][0] += af[u] * bf.x;
                acc[u][1] += af[u] * bf.y;
                acc[u][2] += af[u] * bf.z;
                acc[u][3] += af[u] * bf.w;
            }
        }
        __syncthreads();
    }

    // store fp16 h
#pragma unroll
    for (int u = 0; u < 4; u++) {
        __half2 hp[2];
        hp[0] = __floats2half2_rn(acc[u][0], acc[u][1]);
        hp[1] = __floats2half2_rn(acc[u][2], acc[u][3]);
        *(uint2*)(g_h16 + (size_t)(m0 + row + u) * 256 + n0 + col) = *(uint2*)hp;
    }

    // fused scores: this block's 64 cols == head hd
    const int hd = n0 >> 6;
    float sip[4], sjp[4];
#pragma unroll
    for (int u = 0; u < 4; u++) {
        sip[u] = 0.f; sjp[u] = 0.f;
#pragma unroll
        for (int v = 0; v < 4; v++) {
            int d = col + v;
            sip[u] += acc[u][v] * a[d];
            sjp[u] += acc[u][v] * a[64 + d];
        }
    }
    // reduce over the 16 threads sharing a row group (16-lane halves of warps)
#pragma unroll
    for (int u = 0; u < 4; u++) {
#pragma unroll
        for (int o = 8; o; o >>= 1) {
            sip[u] += __shfl_xor_sync(0xFFFFFFFFu, sip[u], o);
            sjp[u] += __shfl_xor_sync(0xFFFFFFFFu, sjp[u], o);
        }
    }
    if ((tid & 15) == 0) {
#pragma unroll
        for (int u = 0; u < 4; u++) {
            int o = hd * BN + m0 + row + u;
            float si = sip[u], sj = sjp[u];
            g_si[o] = si;
            g_sj[o] = sj;
            g_Ei[o] = __expf(si);
            g_Fi[o] = __expf(0.2f * si);
            g_Ej[o] = __expf(sj);
            g_Fj[o] = __expf(0.2f * sj);
        }
    }
}

// ---------------------------------------------------------------------------
// Kernel C: tensor-core masked-softmax aggregation, double-buffered cp.async.
// Block = (b, 64-row i-tile), 512 threads = 16 warps = 4 i-groups x 4 heads.
// Adjacency staged through smem. Ones column -> denominator via 9th mma tile.
// ---------------------------------------------------------------------------
#define BS_STRIDE 264                                  // halves/row (256 + ones + pad)
#define ADJ_STRIDE 68                                  // ints/row (64 + pad, 16B-aligned)
#define OFF_BS   0                                     // 2 x 64 x 264 x 2B = 67584
#define OFF_ADJ  67584                                 // 2 x 64 x 68 x 4B = 34816
#define OFF_SJ   102400                                // float [4][1024] = 16384
#define OFF_EF   118784                                // half2 [4][1024] = 16384
#define SM_TOTAL 135168

__global__ void k_aggr(const int* __restrict__ adj,
                       float* __restrict__ out) {
    extern __shared__ char smem[];
    __half*  Bs   = (__half*)(smem + OFF_BS);           // [2][64][BS_STRIDE]
    int*     adjS = (int*)(smem + OFF_ADJ);             // [2][64][ADJ_STRIDE]
    float*   sjs  = (float*)(smem + OFF_SJ);            // [h][j]
    __half2* EFs  = (__half2*)(smem + OFF_EF);          // [h][j] = (Ej, Fj)

    const int tid  = threadIdx.x;
    const int lane = tid & 31;
    const int warp = tid >> 5;
    const int wi   = warp & 3;            // i-group (16 rows)
    const int hh   = warp >> 2;           // head
    const int b    = blockIdx.y;
    const int i0   = blockIdx.x * 64;

    // preload per-(b,h) j-side scalars
    for (int idx = tid; idx < NH * NN; idx += 512) {
        int h = idx >> 10, j = idx & 1023;
        int o = h * BN + b * NN + j;
        sjs[idx] = g_sj[o];
        EFs[idx] = __floats2half2_rn(g_Ej[o], g_Fj[o]);
    }
    // ones columns in both buffers
    if (tid < 128) {
        int buf = tid >> 6, r = tid & 63;
        __half* p = Bs + (size_t)buf * 64 * BS_STRIDE + r * BS_STRIDE;
        p[256] = __float2half(1.0f);
#pragma unroll
        for (int c = 257; c < 264; c++) p[c] = __float2half(0.0f);
    }

    // per-thread i-side scalars
    const int hoff = hh * BN + b * NN;
    const int ilo = wi * 16 + (lane >> 2);      // local row 0..15
    const int ihi = ilo + 8;
    const float si_lo = g_si[hoff + i0 + ilo];
    const float Ei_lo = g_Ei[hoff + i0 + ilo];
    const float Fi_lo = g_Fi[hoff + i0 + ilo];
    const float si_hi = g_si[hoff + i0 + ihi];
    const float Ei_hi = g_Ei[hoff + i0 + ihi];
    const float Fi_hi = g_Fi[hoff + i0 + ihi];

    const float*   sjp = sjs + hh * NN;
    const __half2* efp = EFs + hh * NN;
    const __half*  h16b = g_h16 + (size_t)b * NN * 256;
    const int*     adjb = adj + (size_t)b * NN * NN;
    const int jcol = (lane & 3) * 2;

    float acc[9][4];
#pragma unroll
    for (int t = 0; t < 9; t++)
#pragma unroll
        for (int v = 0; v < 4; v++) acc[t][v] = 0.f;

    // cp.async source/dest precompute (per-thread fixed roles)
    const int bs_row = tid >> 3;                 // 0..63
    const int bs_seg = (tid & 7) * 32;           // halves
    const int aj_row = tid >> 3;                 // 0..63
    const int aj_col = (tid & 7) * 8;            // ints

    // issue chunk 0
    {
        const __half* src = h16b + (size_t)bs_row * 256 + bs_seg;
        unsigned dst = (unsigned)__cvta_generic_to_shared(Bs + bs_row * BS_STRIDE + bs_seg);
#pragma unroll
        for (int q = 0; q < 4; q++) cp16(dst + q * 16, src + q * 8);
        const int* asrc = adjb + (size_t)(i0 + aj_row) * NN + aj_col;
        unsigned adst = (unsigned)__cvta_generic_to_shared(adjS + aj_row * ADJ_STRIDE + aj_col);
        cp16(adst, asrc);
        cp16(adst + 16, asrc + 4);
        cp_commit();
    }

    for (int c = 0; c < 16; c++) {
        const int buf = c & 1;
        __half* BsC   = Bs + (size_t)buf * 64 * BS_STRIDE;
        const int* adjC = adjS + buf * 64 * ADJ_STRIDE;

        cp_wait0();
        __syncthreads();     // chunk c ready everywhere; chunk c-1 compute done

        if (c < 15) {        // issue chunk c+1 into the other buffer
            const int j0n = (c + 1) * 64;
            __half* BsN = Bs + (size_t)(1 - buf) * 64 * BS_STRIDE;
            int* adjN = adjS + (1 - buf) * 64 * ADJ_STRIDE;
            const __half* src = h16b + (size_t)(j0n + bs_row) * 256 + bs_seg;
            unsigned dst = (unsigned)__cvta_generic_to_shared(BsN + bs_row * BS_STRIDE + bs_seg);
#pragma unroll
            for (int q = 0; q < 4; q++) cp16(dst + q * 16, src + q * 8);
            const int* asrc = adjb + (size_t)(i0 + aj_row) * NN + j0n + aj_col;
            unsigned adst = (unsigned)__cvta_generic_to_shared(adjN + aj_row * ADJ_STRIDE + aj_col);
            cp16(adst, asrc);
            cp16(adst + 16, asrc + 4);
            cp_commit();
        }

        const int j0 = c * 64;
#pragma unroll
        for (int ks = 0; ks < 4; ks++) {
            const int jl = ks * 16 + jcol;       // local j (even)
            const int jg = j0 + jl;              // global j
            int2 alo0 = *(const int2*)(adjC + ilo * ADJ_STRIDE + jl);
            int2 alo8 = *(const int2*)(adjC + ilo * ADJ_STRIDE + jl + 8);
            int2 ahi0 = *(const int2*)(adjC + ihi * ADJ_STRIDE + jl);
            int2 ahi8 = *(const int2*)(adjC + ihi * ADJ_STRIDE + jl + 8);

            unsigned a0, a1, a2, a3;
            {
                float sj0 = sjp[jg], sj1 = sjp[jg + 1];
                __half2 e0 = efp[jg], e1 = efp[jg + 1];
                float Ej0 = __low2float(e0), Fj0 = __high2float(e0);
                float Ej1 = __low2float(e1), Fj1 = __high2float(e1);
                float w0 = alo0.x ? ((si_lo + sj0 >= 0.f) ? Ei_lo * Ej0 : Fi_lo * Fj0) : 0.f;
                float w1 = alo0.y ? ((si_lo + sj1 >= 0.f) ? Ei_lo * Ej1 : Fi_lo * Fj1) : 0.f;
                __half2 p = __floats2half2_rn(w0, w1);
                a0 = *(unsigned*)&p;
                float v0 = ahi0.x ? ((si_hi + sj0 >= 0.f) ? Ei_hi * Ej0 : Fi_hi * Fj0) : 0.f;
                float v1 = ahi0.y ? ((si_hi + sj1 >= 0.f) ? Ei_hi * Ej1 : Fi_hi * Fj1) : 0.f;
                __half2 q = __floats2half2_rn(v0, v1);
                a1 = *(unsigned*)&q;
            }
            {
                float sj0 = sjp[jg + 8], sj1 = sjp[jg + 9];
                __half2 e0 = efp[jg + 8], e1 = efp[jg + 9];
                float Ej0 = __low2float(e0), Fj0 = __high2float(e0);
                float Ej1 = __low2float(e1), Fj1 = __high2float(e1);
                float w0 = alo8.x ? ((si_lo + sj0 >= 0.f) ? Ei_lo * Ej0 : Fi_lo * Fj0) : 0.f;
                float w1 = alo8.y ? ((si_lo + sj1 >= 0.f) ? Ei_lo * Ej1 : Fi_lo * Fj1) : 0.f;
                __half2 p = __floats2half2_rn(w0, w1);
                a2 = *(unsigned*)&p;
                float v0 = ahi8.x ? ((si_hi + sj0 >= 0.f) ? Ei_hi * Ej0 : Fi_hi * Fj0) : 0.f;
                float v1 = ahi8.y ? ((si_hi + sj1 >= 0.f) ? Ei_hi * Ej1 : Fi_hi * Fj1) : 0.f;
                __half2 q = __floats2half2_rn(v0, v1);
                a3 = *(unsigned*)&q;
            }

            const int krow = ks * 16 + (lane & 15);
            unsigned bt[9][2];
#pragma unroll
            for (int p = 0; p < 4; p++) {
                int nb = hh * 64 + p * 16 + ((lane >> 4) << 3);
                unsigned addr = (unsigned)__cvta_generic_to_shared(
                    BsC + krow * BS_STRIDE + nb);
                asm volatile(
                    "ldmatrix.sync.aligned.m8n8.x4.trans.shared.b16 {%0,%1,%2,%3}, [%4];"
                    : "=r"(bt[2 * p][0]), "=r"(bt[2 * p][1]),
                      "=r"(bt[2 * p + 1][0]), "=r"(bt[2 * p + 1][1])
                    : "r"(addr));
            }
            {
                unsigned addr = (unsigned)__cvta_generic_to_shared(
                    BsC + krow * BS_STRIDE + 256);
                asm volatile(
                    "ldmatrix.sync.aligned.m8n8.x2.trans.shared.b16 {%0,%1}, [%2];"
                    : "=r"(bt[8][0]), "=r"(bt[8][1]) : "r"(addr));
            }

#pragma unroll
            for (int t = 0; t < 9; t++) {
                asm volatile(
                    "mma.sync.aligned.m16n8k16.row.col.f32.f16.f16.f32 "
                    "{%0,%1,%2,%3}, {%4,%5,%6,%7}, {%8,%9}, {%0,%1,%2,%3};"
                    : "+f"(acc[t][0]), "+f"(acc[t][1]), "+f"(acc[t][2]), "+f"(acc[t][3])
                    : "r"(a0), "r"(a1), "r"(a2), "r"(a3),
                      "r"(bt[t][0]), "r"(bt[t][1]));
            }
        }
        __syncthreads();     // compute done before buffer refill next iter
    }

    // epilogue: denominators from ones tile, divide, store
    float den_lo = __shfl_sync(0xFFFFFFFFu, acc[8][0], lane & 28);
    float den_hi = __shfl_sync(0xFFFFFFFFu, acc[8][2], lane & 28);
    float inv_lo = 1.0f / den_lo;
    float inv_hi = 1.0f / den_hi;

    const size_t row_lo = (size_t)b * NN + i0 + ilo;
    const size_t row_hi = (size_t)b * NN + i0 + ihi;
#pragma unroll
    for (int t = 0; t < 8; t++) {
        int col = hh * 64 + t * 8 + (lane & 3) * 2;
        float2 vlo = make_float2(acc[t][0] * inv_lo, acc[t][1] * inv_lo);
        float2 vhi = make_float2(acc[t][2] * inv_hi, acc[t][3] * inv_hi);
        *(float2*)(out + row_lo * 256 + col) = vlo;
        *(float2*)(out + row_hi * 256 + col) = vhi;
    }
}

// ---------------------------------------------------------------------------
extern "C" void kernel_launch(void* const* d_in, const int* in_sizes, int n_in,
                              void* d_out, int out_size) {
    const float* x   = (const float*)d_in[0];   // [8,1024,128]
    const int*   adj = (const int*)d_in[1];     // [8,1024,1024]
    const float* W   = (const float*)d_in[2];   // [128,256]
    const float* a   = (const float*)d_in[3];   // [128]
    float* out = (float*)d_out;                 // [8,1024,256]

    cudaFuncSetAttribute(k_aggr, cudaFuncAttributeMaxDynamicSharedMemorySize,
                         SM_TOTAL);

    k_gemm<<<dim3(BN / 64, OUTF / 64), 256>>>(x, W, a);
    k_aggr<<<dim3(NN / 64, BB), 512, SM_TOTAL>>>(adj, out);
}

// round 4
// speedup vs baseline: 3.0620x; 1.0437x over previous
#include <cuda_runtime.h>
#include <cuda_fp16.h>
#include <cuda_bf16.h>

// Problem constants (fixed by reference setup_inputs)
#define BB 8
#define NN 1024
#define BN 8192          // B*N
#define INF 128
#define OUTF 256
#define NH 4
#define DD 64

// Scratch (device globals)
__device__ __half g_h16[BN * OUTF];     // h in fp16 (MMA B operand)
__device__ __half g_sih[NH * BN];       // i-side: s_i, e^{s_i}, e^{0.2 s_i}
__device__ __half g_Eih[NH * BN];
__device__ __half g_Fih[NH * BN];
__device__ __half g_sjh[NH * BN];       // j-side
__device__ __half g_Ejh[NH * BN];
__device__ __half g_Fjh[NH * BN];

// cp.async helpers
__device__ __forceinline__ void cp16(unsigned dst, const void* src) {
    asm volatile("cp.async.cg.shared.global [%0], [%1], 16;" :: "r"(dst), "l"(src));
}
__device__ __forceinline__ void cp_commit() {
    asm volatile("cp.async.commit_group;");
}
__device__ __forceinline__ void cp_wait0() {
    asm volatile("cp.async.wait_group 0;");
}

// f16x2-as-u32 helpers (branchless w generation)
__device__ __forceinline__ unsigned u_hadd2(unsigned a, unsigned b) {
    unsigned r; asm("add.f16x2 %0,%1,%2;" : "=r"(r) : "r"(a), "r"(b)); return r;
}
__device__ __forceinline__ unsigned u_hmul2(unsigned a, unsigned b) {
    unsigned r; asm("mul.f16x2 %0,%1,%2;" : "=r"(r) : "r"(a), "r"(b)); return r;
}
__device__ __forceinline__ unsigned u_hge0_mask(unsigned a) {
    unsigned r; asm("set.ge.u32.f16x2 %0,%1,%2;" : "=r"(r) : "r"(a), "r"(0u)); return r;
}
// w for 2 adjacent j: select e^{si}e^{sj} vs e^{.2si}e^{.2sj} by sign(si+sj), mask by adjacency
__device__ __forceinline__ unsigned wgen2(unsigned si2, unsigned Ei2, unsigned Fi2,
                                          unsigned sj2, unsigned Ej2, unsigned Fj2,
                                          unsigned am) {
    unsigned t  = u_hadd2(si2, sj2);
    unsigned m  = u_hge0_mask(t);
    unsigned EE = u_hmul2(Ei2, Ej2);
    unsigned FF = u_hmul2(Fi2, Fj2);
    return ((m & EE) | (~m & FF)) & am;
}

// ---------------------------------------------------------------------------
// Kernel A: SGEMM h = x @ W (fp32 math, fp16 store) FUSED with per-node
// attention scores; all score/exp factors stored directly as fp16.
// 64x64 tiles, BK=32, 256 threads, 4x4 microtile.
// ---------------------------------------------------------------------------
__global__ __launch_bounds__(256) void k_gemm(const float* __restrict__ x,
                                              const float* __restrict__ W,
                                              const float* __restrict__ a) {
    __shared__ float As[32 * 65];     // [k][m]
    __shared__ float Bs[32 * 68];     // [k][n]

    const int tid = threadIdx.x;
    const int m0 = blockIdx.x * 64;
    const int n0 = blockIdx.y * 64;
    const int row = (tid >> 4) * 4;
    const int col = (tid & 15) * 4;

    float acc[4][4];
#pragma unroll
    for (int u = 0; u < 4; u++)
#pragma unroll
        for (int v = 0; v < 4; v++) acc[u][v] = 0.f;

    for (int k0 = 0; k0 < 128; k0 += 32) {
#pragma unroll
        for (int q = 0; q < 2; q++) {
            int f = tid + q * 256;
            int r = f >> 3;
            int c4 = (f & 7) * 4;
            float4 v = *(const float4*)(x + (size_t)(m0 + r) * 128 + k0 + c4);
            As[(c4 + 0) * 65 + r] = v.x;
            As[(c4 + 1) * 65 + r] = v.y;
            As[(c4 + 2) * 65 + r] = v.z;
            As[(c4 + 3) * 65 + r] = v.w;
        }
#pragma unroll
        for (int q = 0; q < 2; q++) {
            int f = tid + q * 256;
            int r = f >> 4;
            int c = (f & 15) * 4;
            *(float4*)&Bs[r * 68 + c] = *(const float4*)(W + (size_t)(k0 + r) * 256 + n0 + c);
        }
        __syncthreads();

#pragma unroll
        for (int k = 0; k < 32; k++) {
            float af[4];
#pragma unroll
            for (int u = 0; u < 4; u++) af[u] = As[k * 65 + row + u];
            float4 bf = *(const float4*)&Bs[k * 68 + col];
#pragma unroll
            for (int u = 0; u < 4; u++) {
                acc[u][0] += af[u] * bf.x;
                acc[u][1] += af[u] * bf.y;
                acc[u][2] += af[u] * bf.z;
                acc[u][3] += af[u] * bf.w;
            }
        }
        __syncthreads();
    }

    // store fp16 h
#pragma unroll
    for (int u = 0; u < 4; u++) {
        __half2 hp[2];
        hp[0] = __floats2half2_rn(acc[u][0], acc[u][1]);
        hp[1] = __floats2half2_rn(acc[u][2], acc[u][3]);
        *(uint2*)(g_h16 + (size_t)(m0 + row + u) * 256 + n0 + col) = *(uint2*)hp;
    }

    // fused scores: this block's 64 cols == one head
    const int hd = n0 >> 6;
    float sip[4], sjp[4];
#pragma unroll
    for (int u = 0; u < 4; u++) {
        sip[u] = 0.f; sjp[u] = 0.f;
#pragma unroll
        for (int v = 0; v < 4; v++) {
            int d = col + v;
            sip[u] += acc[u][v] * a[d];
            sjp[u] += acc[u][v] * a[64 + d];
        }
    }
#pragma unroll
    for (int u = 0; u < 4; u++) {
#pragma unroll
        for (int o = 8; o; o >>= 1) {
            sip[u] += __shfl_xor_sync(0xFFFFFFFFu, sip[u], o);
            sjp[u] += __shfl_xor_sync(0xFFFFFFFFu, sjp[u], o);
        }
    }
    if ((tid & 15) == 0) {
#pragma unroll
        for (int u = 0; u < 4; u++) {
            int o = hd * BN + m0 + row + u;
            float si = sip[u], sj = sjp[u];
            g_sih[o] = __float2half_rn(si);
            g_Eih[o] = __float2half_rn(__expf(si));
            g_Fih[o] = __float2half_rn(__expf(0.2f * si));
            g_sjh[o] = __float2half_rn(sj);
            g_Ejh[o] = __float2half_rn(__expf(sj));
            g_Fjh[o] = __float2half_rn(__expf(0.2f * sj));
        }
    }
}

// ---------------------------------------------------------------------------
// Kernel C: tensor-core masked-softmax aggregation, double-buffered cp.async,
// branchless fp16 w-generation. Block = (b, 64 i-rows), 512 thr = 16 warps
// = 4 i-groups x 4 heads. Ones column -> denominator via 9th mma tile.
// ---------------------------------------------------------------------------
#define BS_STRIDE 264                         // halves/row (256 + ones + pad)
#define ADJ_STRIDE 68                         // ints/row (64 + pad)
#define OFF_BS   0                            // 2*64*264*2   = 67584
#define OFF_ADJ  67584                        // 2*64*68*4    = 34816
#define OFF_SJH  102400                       // [4][1024] half = 8192
#define OFF_EJH  110592                       // 8192
#define OFF_FJH  118784                       // 8192
#define SM_TOTAL 126976

__global__ void k_aggr(const int* __restrict__ adj,
                       float* __restrict__ out) {
    extern __shared__ char smem[];
    __half* Bs    = (__half*)(smem + OFF_BS);     // [2][64][BS_STRIDE]
    int*    adjS  = (int*)(smem + OFF_ADJ);       // [2][64][ADJ_STRIDE]
    __half* sjh_s = (__half*)(smem + OFF_SJH);    // [h][j]
    __half* Ejh_s = (__half*)(smem + OFF_EJH);
    __half* Fjh_s = (__half*)(smem + OFF_FJH);

    const int tid  = threadIdx.x;
    const int lane = tid & 31;
    const int warp = tid >> 5;
    const int wi   = warp & 3;            // i-group (16 rows)
    const int hh   = warp >> 2;           // head
    const int b    = blockIdx.y;
    const int i0   = blockIdx.x * 64;

    // preload per-(b,h) j-side scalars (vectorized: 1 uint4 per array per thread)
    {
        int h = tid >> 7, j8 = (tid & 127) * 8;
        int o = h * BN + b * NN + j8;
        *(uint4*)(sjh_s + h * NN + j8) = *(const uint4*)(g_sjh + o);
        *(uint4*)(Ejh_s + h * NN + j8) = *(const uint4*)(g_Ejh + o);
        *(uint4*)(Fjh_s + h * NN + j8) = *(const uint4*)(g_Fjh + o);
    }
    // ones columns in both buffers
    if (tid < 128) {
        int buf = tid >> 6, r = tid & 63;
        __half* p = Bs + (size_t)buf * 64 * BS_STRIDE + r * BS_STRIDE;
        p[256] = __float2half(1.0f);
#pragma unroll
        for (int c = 257; c < 264; c++) p[c] = __float2half(0.0f);
    }

    // per-thread i-side scalar broadcasts (rows ilo / ihi of this warp's m16)
    const int hoff = hh * BN + b * NN;
    const int ilo = wi * 16 + (lane >> 2);
    const int ihi = ilo + 8;
    unsigned si2_lo, Ei2_lo, Fi2_lo, si2_hi, Ei2_hi, Fi2_hi;
    {
        __half2 v;
        v = __half2half2(g_sih[hoff + i0 + ilo]); si2_lo = *(unsigned*)&v;
        v = __half2half2(g_Eih[hoff + i0 + ilo]); Ei2_lo = *(unsigned*)&v;
        v = __half2half2(g_Fih[hoff + i0 + ilo]); Fi2_lo = *(unsigned*)&v;
        v = __half2half2(g_sih[hoff + i0 + ihi]); si2_hi = *(unsigned*)&v;
        v = __half2half2(g_Eih[hoff + i0 + ihi]); Ei2_hi = *(unsigned*)&v;
        v = __half2half2(g_Fih[hoff + i0 + ihi]); Fi2_hi = *(unsigned*)&v;
    }

    const __half* h16b = g_h16 + (size_t)b * NN * 256;
    const int*    adjb = adj + (size_t)b * NN * NN;
    const int jcol = (lane & 3) * 2;
    const __half* sjhH = sjh_s + hh * NN;
    const __half* EjhH = Ejh_s + hh * NN;
    const __half* FjhH = Fjh_s + hh * NN;

    float acc[9][4];
#pragma unroll
    for (int t = 0; t < 9; t++)
#pragma unroll
        for (int v = 0; v < 4; v++) acc[t][v] = 0.f;

    // cp.async roles
    const int bs_row = tid >> 3;
    const int bs_seg = (tid & 7) * 32;
    const int aj_row = tid >> 3;
    const int aj_col = (tid & 7) * 8;

    // issue chunk 0
    {
        const __half* src = h16b + (size_t)bs_row * 256 + bs_seg;
        unsigned dst = (unsigned)__cvta_generic_to_shared(Bs + bs_row * BS_STRIDE + bs_seg);
#pragma unroll
        for (int q = 0; q < 4; q++) cp16(dst + q * 16, src + q * 8);
        const int* asrc = adjb + (size_t)(i0 + aj_row) * NN + aj_col;
        unsigned adst = (unsigned)__cvta_generic_to_shared(adjS + aj_row * ADJ_STRIDE + aj_col);
        cp16(adst, asrc);
        cp16(adst + 16, asrc + 4);
        cp_commit();
    }

    for (int c = 0; c < 16; c++) {
        const int buf = c & 1;
        __half* BsC = Bs + (size_t)buf * 64 * BS_STRIDE;
        const int* adjC = adjS + buf * 64 * ADJ_STRIDE;

        cp_wait0();
        __syncthreads();

        if (c < 15) {
            const int j0n = (c + 1) * 64;
            __half* BsN = Bs + (size_t)(1 - buf) * 64 * BS_STRIDE;
            int* adjN = adjS + (1 - buf) * 64 * ADJ_STRIDE;
            const __half* src = h16b + (size_t)(j0n + bs_row) * 256 + bs_seg;
            unsigned dst = (unsigned)__cvta_generic_to_shared(BsN + bs_row * BS_STRIDE + bs_seg);
#pragma unroll
            for (int q = 0; q < 4; q++) cp16(dst + q * 16, src + q * 8);
            const int* asrc = adjb + (size_t)(i0 + aj_row) * NN + j0n + aj_col;
            unsigned adst = (unsigned)__cvta_generic_to_shared(adjN + aj_row * ADJ_STRIDE + aj_col);
            cp16(adst, asrc);
            cp16(adst + 16, asrc + 4);
            cp_commit();
        }

        const int j0 = c * 64;
#pragma unroll
        for (int ks = 0; ks < 4; ks++) {
            const int jl = ks * 16 + jcol;       // local j (even)
            const int jg = j0 + jl;              // global j
            // adjacency (int pairs) and j-side half2 factors
            int2 alo0 = *(const int2*)(adjC + ilo * ADJ_STRIDE + jl);
            int2 alo8 = *(const int2*)(adjC + ilo * ADJ_STRIDE + jl + 8);
            int2 ahi0 = *(const int2*)(adjC + ihi * ADJ_STRIDE + jl);
            int2 ahi8 = *(const int2*)(adjC + ihi * ADJ_STRIDE + jl + 8);
            unsigned sj0 = *(const unsigned*)(sjhH + jg);
            unsigned Ej0 = *(const unsigned*)(EjhH + jg);
            unsigned Fj0 = *(const unsigned*)(FjhH + jg);
            unsigned sj8 = *(const unsigned*)(sjhH + jg + 8);
            unsigned Ej8 = *(const unsigned*)(EjhH + jg + 8);
            unsigned Fj8 = *(const unsigned*)(FjhH + jg + 8);

            unsigned am_lo0 = __byte_perm((unsigned)(-alo0.x), (unsigned)(-alo0.y), 0x5410);
            unsigned am_hi0 = __byte_perm((unsigned)(-ahi0.x), (unsigned)(-ahi0.y), 0x5410);
            unsigned am_lo8 = __byte_perm((unsigned)(-alo8.x), (unsigned)(-alo8.y), 0x5410);
            unsigned am_hi8 = __byte_perm((unsigned)(-ahi8.x), (unsigned)(-ahi8.y), 0x5410);

            unsigned a0 = wgen2(si2_lo, Ei2_lo, Fi2_lo, sj0, Ej0, Fj0, am_lo0);
            unsigned a1 = wgen2(si2_hi, Ei2_hi, Fi2_hi, sj0, Ej0, Fj0, am_hi0);
            unsigned a2 = wgen2(si2_lo, Ei2_lo, Fi2_lo, sj8, Ej8, Fj8, am_lo8);
            unsigned a3 = wgen2(si2_hi, Ei2_hi, Fi2_hi, sj8, Ej8, Fj8, am_hi8);

            const int krow = ks * 16 + (lane & 15);
            unsigned bt[9][2];
#pragma unroll
            for (int p = 0; p < 4; p++) {
                int nb = hh * 64 + p * 16 + ((lane >> 4) << 3);
                unsigned addr = (unsigned)__cvta_generic_to_shared(
                    BsC + krow * BS_STRIDE + nb);
                asm volatile(
                    "ldmatrix.sync.aligned.m8n8.x4.trans.shared.b16 {%0,%1,%2,%3}, [%4];"
                    : "=r"(bt[2 * p][0]), "=r"(bt[2 * p][1]),
                      "=r"(bt[2 * p + 1][0]), "=r"(bt[2 * p + 1][1])
                    : "r"(addr));
            }
            {
                unsigned addr = (unsigned)__cvta_generic_to_shared(
                    BsC + krow * BS_STRIDE + 256);
                asm volatile(
                    "ldmatrix.sync.aligned.m8n8.x2.trans.shared.b16 {%0,%1}, [%2];"
                    : "=r"(bt[8][0]), "=r"(bt[8][1]) : "r"(addr));
            }

#pragma unroll
            for (int t = 0; t < 9; t++) {
                asm volatile(
                    "mma.sync.aligned.m16n8k16.row.col.f32.f16.f16.f32 "
                    "{%0,%1,%2,%3}, {%4,%5,%6,%7}, {%8,%9}, {%0,%1,%2,%3};"
                    : "+f"(acc[t][0]), "+f"(acc[t][1]), "+f"(acc[t][2]), "+f"(acc[t][3])
                    : "r"(a0), "r"(a1), "r"(a2), "r"(a3),
                      "r"(bt[t][0]), "r"(bt[t][1]));
            }
        }
        __syncthreads();
    }

    // epilogue: denominators from ones tile, divide, store
    float den_lo = __shfl_sync(0xFFFFFFFFu, acc[8][0], lane & 28);
    float den_hi = __shfl_sync(0xFFFFFFFFu, acc[8][2], lane & 28);
    float inv_lo = 1.0f / den_lo;
    float inv_hi = 1.0f / den_hi;

    const size_t row_lo = (size_t)b * NN + i0 + ilo;
    const size_t row_hi = (size_t)b * NN + i0 + ihi;
#pragma unroll
    for (int t = 0; t < 8; t++) {
        int col = hh * 64 + t * 8 + (lane & 3) * 2;
        float2 vlo = make_float2(acc[t][0] * inv_lo, acc[t][1] * inv_lo);
        float2 vhi = make_float2(acc[t][2] * inv_hi, acc[t][3] * inv_hi);
        *(float2*)(out + row_lo * 256 + col) = vlo;
        *(float2*)(out + row_hi * 256 + col) = vhi;
    }
}

// ---------------------------------------------------------------------------
extern "C" void kernel_launch(void* const* d_in, const int* in_sizes, int n_in,
                              void* d_out, int out_size) {
    const float* x   = (const float*)d_in[0];   // [8,1024,128]
    const int*   adj = (const int*)d_in[1];     // [8,1024,1024]
    const float* W   = (const float*)d_in[2];   // [128,256]
    const float* a   = (const float*)d_in[3];   // [128]
    float* out = (float*)d_out;                 // [8,1024,256]

    cudaFuncSetAttribute(k_aggr, cudaFuncAttributeMaxDynamicSharedMemorySize,
                         SM_TOTAL);

    k_gemm<<<dim3(BN / 64, OUTF / 64), 256>>>(x, W, a);
    k_aggr<<<dim3(NN / 64, BB), 512, SM_TOTAL>>>(adj, out);
}